// round 13
// baseline (speedup 1.0000x reference)
#include <cuda_runtime.h>
#include <cuda_bf16.h>
#include <cstdint>

#define E_EDGES 1024
#define N_NODES 8192
#define ZD      256
#define KK_RANK 819
#define DE_NOM  818
#define W0      (1.0f/818.0f)

// ---- scratch ----
__device__ float    g_simi[(size_t)E_EDGES * N_NODES];  // 32 MB [e][n]
__device__ unsigned g_Hbt[256 * E_EDGES];                // bitmask [n/32][e]
__device__ unsigned g_Hn[(size_t)N_NODES * 32];          // node-major edge bits [n][32]
__device__ float    g_DV2[N_NODES];
__device__ int      g_nDev;
__device__ int      g_devE[E_EDGES];
__device__ int      g_devDE[E_EDGES];

// packed fp32x2 FMA (Blackwell)
__device__ __forceinline__ void ffma2(unsigned long long &d,
                                      unsigned long long a, unsigned long long b)
{
    asm volatile("fma.rn.f32x2 %0, %1, %2, %0;" : "+l"(d) : "l"(a), "l"(b));
}
__device__ __forceinline__ unsigned long long pack2(float v)
{
    unsigned long long r;
    asm("mov.b64 %0, {%1, %1};" : "=l"(r) : "f"(v));
    return r;
}
__device__ __forceinline__ unsigned lop3_xor3(unsigned a, unsigned b, unsigned c)
{
    unsigned d;
    asm("lop3.b32 %0, %1, %2, %3, 0x96;" : "=r"(d) : "r"(a), "r"(b), "r"(c));
    return d;
}
__device__ __forceinline__ unsigned lop3_maj(unsigned a, unsigned b, unsigned c)
{
    unsigned d;
    asm("lop3.b32 %0, %1, %2, %3, 0xE8;" : "=r"(d) : "r"(a), "r"(b), "r"(c));
    return d;
}

// =====================================================================
// Kernel 1: simi = hyper_clss @ x^T  (fp32, f32x2-packed FMA)
// =====================================================================
__global__ __launch_bounds__(256) void k_simi(
    const float* __restrict__ x, const int* __restrict__ y,
    const float* __restrict__ hp)
{
    if (blockIdx.x == 0 && blockIdx.y == 0 && threadIdx.x == 0) g_nDev = 0;

    __shared__ float As[32][65];
    __shared__ float Bs[32][130];
    const int be = blockIdx.y * 64, bn = blockIdx.x * 128;
    const int tid = threadIdx.x;
    const int ty = tid >> 4, tx = tid & 15;

    unsigned long long acc2[4][4];
    #pragma unroll
    for (int i = 0; i < 4; i++)
        #pragma unroll
        for (int j = 0; j < 4; j++) acc2[i][j] = 0ull;

    for (int k0 = 0; k0 < ZD; k0 += 32) {
        #pragma unroll
        for (int p = 0; p < 2; p++) {
            int idx = tid + p * 256;
            int e = idx >> 3, k4 = (idx & 7) << 2;
            int ge = be + e;
            int row = y[ge >> 4] * 16 + (ge & 15);
            float4 v = *(const float4*)(hp + (size_t)row * ZD + k0 + k4);
            As[k4+0][e] = v.x; As[k4+1][e] = v.y; As[k4+2][e] = v.z; As[k4+3][e] = v.w;
        }
        #pragma unroll
        for (int p = 0; p < 4; p++) {
            int idx = tid + p * 256;
            int n = idx >> 3, k4 = (idx & 7) << 2;
            float4 v = *(const float4*)(x + (size_t)(bn + n) * ZD + k0 + k4);
            Bs[k4+0][n] = v.x; Bs[k4+1][n] = v.y; Bs[k4+2][n] = v.z; Bs[k4+3][n] = v.w;
        }
        __syncthreads();
        #pragma unroll
        for (int k = 0; k < 32; k++) {
            unsigned long long ad[4], bd[4];
            #pragma unroll
            for (int mi = 0; mi < 4; mi++) ad[mi] = pack2(As[k][ty + 16 * mi]);
            #pragma unroll
            for (int nj = 0; nj < 4; nj++)
                bd[nj] = *(const unsigned long long*)&Bs[k][2 * tx + 32 * nj];
            #pragma unroll
            for (int mi = 0; mi < 4; mi++)
                #pragma unroll
                for (int nj = 0; nj < 4; nj++)
                    ffma2(acc2[mi][nj], ad[mi], bd[nj]);
        }
        __syncthreads();
    }
    #pragma unroll
    for (int mi = 0; mi < 4; mi++)
        #pragma unroll
        for (int nj = 0; nj < 4; nj++) {
            unsigned lo = (unsigned)(acc2[mi][nj] & 0xFFFFFFFFull);
            unsigned hi = (unsigned)(acc2[mi][nj] >> 32);
            float2 v = make_float2(__uint_as_float(lo), __uint_as_float(hi));
            *(float2*)&g_simi[(size_t)(be + ty + 16 * mi) * N_NODES + bn + 2 * tx + 32 * nj] = v;
        }
}

// =====================================================================
// Kernel 2: exact radix select (race-free winner update)
// =====================================================================
__global__ __launch_bounds__(256) void k_select()
{
    __shared__ unsigned su[N_NODES];
    __shared__ unsigned hist[256];
    __shared__ unsigned sfx[256];
    __shared__ unsigned s_bin, s_r, s_above;

    const int e = blockIdx.x;
    const int t = threadIdx.x;
    const float* row = g_simi + (size_t)e * N_NODES;

    #pragma unroll 4
    for (int i = 0; i < 32; i++) {
        unsigned b = __float_as_uint(row[i * 256 + t]);
        su[i * 256 + t] = (b & 0x80000000u) ? ~b : (b | 0x80000000u);
    }
    if (t == 0) { s_r = KK_RANK; s_above = 0; }
    __syncthreads();

    unsigned prefix = 0, pmask = 0;
    for (int level = 0; level < 4; level++) {
        int shift = 24 - 8 * level;
        hist[t] = 0;
        __syncthreads();
        #pragma unroll 4
        for (int i = 0; i < 32; i++) {
            unsigned u = su[i * 256 + t];
            if ((u & pmask) == prefix) atomicAdd(&hist[(u >> shift) & 0xFFu], 1u);
        }
        __syncthreads();
        sfx[t] = hist[t];
        __syncthreads();
        #pragma unroll
        for (int off = 1; off < 256; off <<= 1) {
            unsigned v = sfx[t] + ((t + off < 256) ? sfx[t + off] : 0u);
            __syncthreads();
            sfx[t] = v;
            __syncthreads();
        }
        const unsigned r_cur = s_r;
        const unsigned nxt   = (t < 255) ? sfx[t + 1] : 0u;
        const bool winner    = (sfx[t] >= r_cur) && (nxt < r_cur);
        __syncthreads();
        if (winner) {
            s_bin = (unsigned)t;
            s_r = r_cur - nxt;
            s_above += nxt;
        }
        __syncthreads();
        prefix |= (s_bin << shift);
        pmask  |= (0xFFu << shift);
        __syncthreads();
    }

    const unsigned thr = prefix;
    const unsigned de  = s_above;

    unsigned v = 0;
    #pragma unroll
    for (int b = 0; b < 32; b++)
        v |= (su[32 * t + b] > thr) ? (1u << b) : 0u;
    g_Hbt[t * E_EDGES + e] = v;

    if (t == 0 && de != DE_NOM) {
        int idx = atomicAdd(&g_nDev, 1);
        g_devE[idx] = e; g_devDE[idx] = (int)de;
    }
}

// =====================================================================
// Kernel 3: bit transpose -> node-major edge masks g_Hn[n][32] + DV2.
// =====================================================================
__global__ __launch_bounds__(256) void k_pack_dv()
{
    const int w = blockIdx.x;
    const int t = threadIdx.x;
    const int warp = t >> 5, lane = t & 31;
    __shared__ int s_cnt[32];
    if (t < 32) s_cnt[t] = 0;
    __syncthreads();

    int myCnt = 0;
    #pragma unroll
    for (int i = 0; i < 4; i++) {
        int ew = warp + 8 * i;
        unsigned v = g_Hbt[w * E_EDGES + ew * 32 + lane];
        #pragma unroll
        for (int b = 0; b < 32; b++) {
            unsigned word = __ballot_sync(0xFFFFFFFFu, (v >> b) & 1u);
            if (lane == b) {
                g_Hn[(size_t)(w * 32 + b) * 32 + ew] = word;
                myCnt += __popc(word);
            }
        }
    }
    atomicAdd(&s_cnt[lane], myCnt);
    __syncthreads();
    if (t < 32) g_DV2[w * 32 + t] = rsqrtf((float)s_cnt[t]);
}

// =====================================================================
// Kernel 4: O = H^T H via Harley-Seal CSA popcount (exact)
// 128x128 tiles; 512 threads; 8x4 accs; pair-interleaved uint2 smem
// layout (stride 129) -> one LDS.64 feeds each HS-2 step.
// =====================================================================
#define TSTR 132
#define PSTR 129   // uint2 stride: conflict-free b-loads

__global__ __launch_bounds__(512, 1) void k_gemm(float* __restrict__ G)
{
    int b = blockIdx.x;
    int bi = (int)(64.5f - sqrtf(64.5f * 64.5f - 2.0f * (float)b));
    while (64 * bi - bi * (bi - 1) / 2 > b) bi--;
    while (64 * (bi + 1) - (bi + 1) * bi / 2 <= b) bi++;
    const int bj = bi + (b - (64 * bi - bi * (bi - 1) / 2));

    extern __shared__ char dynsm[];
    uint2* spA = (uint2*)dynsm;                 // [16][PSTR] word-pairs (16512 B)
    uint2* spB = spA + 16 * PSTR;               // 16512 B
    float* sT  = (float*)dynsm;                 // [128][TSTR] floats (reuse)

    const int i0 = bi * 128, j0 = bj * 128;
    const int tid = threadIdx.x;
    const int lane = tid & 31;                  // col base
    const int ty = tid >> 5;                    // row base 0..15

    // ---- load tiles: pair-interleave 4 consecutive ew into 2 uint2 ----
    #pragma unroll
    for (int u = 0; u < 2; u++) {
        int idx = tid * 2 + u;                  // 0..1023
        int r = idx >> 3, q = (idx & 7) << 2;   // row, first ew (mult of 4)
        uint4 va = *(const uint4*)(g_Hn + (size_t)(i0 + r) * 32 + q);
        uint4 vb = *(const uint4*)(g_Hn + (size_t)(j0 + r) * 32 + q);
        int p0 = q >> 1;                        // pair index (even)
        spA[(p0    ) * PSTR + r] = make_uint2(va.x, va.y);
        spA[(p0 + 1) * PSTR + r] = make_uint2(va.z, va.w);
        spB[(p0    ) * PSTR + r] = make_uint2(vb.x, vb.y);
        spB[(p0 + 1) * PSTR + r] = make_uint2(vb.z, vb.w);
    }
    __syncthreads();

    int acc[8][4];
    unsigned ones[8][4];
    #pragma unroll
    for (int jm = 0; jm < 8; jm++)
        #pragma unroll
        for (int jn = 0; jn < 4; jn++) { acc[jm][jn] = 0; ones[jm][jn] = 0u; }

    #pragma unroll
    for (int ews = 0; ews < 16; ews++) {
        uint2 a2[8], b2[4];
        #pragma unroll
        for (int jm = 0; jm < 8; jm++) a2[jm] = spA[ews * PSTR + ty + 16 * jm];
        #pragma unroll
        for (int jn = 0; jn < 4; jn++) b2[jn] = spB[ews * PSTR + lane + 32 * jn];
        #pragma unroll
        for (int jm = 0; jm < 8; jm++)
            #pragma unroll
            for (int jn = 0; jn < 4; jn++) {
                unsigned t0 = a2[jm].x & b2[jn].x;
                unsigned t1 = a2[jm].y & b2[jn].y;
                unsigned o  = ones[jm][jn];
                ones[jm][jn] = lop3_xor3(o, t0, t1);
                acc[jm][jn] += __popc(lop3_maj(o, t0, t1));
            }
    }
    #pragma unroll
    for (int jm = 0; jm < 8; jm++)
        #pragma unroll
        for (int jn = 0; jn < 4; jn++)
            acc[jm][jn] = 2 * acc[jm][jn] + __popc(ones[jm][jn]);

    __syncthreads();   // done reading spA/spB before sT reuse

    // ---- epilogue: scale, store block, mirror via smem transpose ----
    const bool offd = (bi != bj);
    #pragma unroll
    for (int jm = 0; jm < 8; jm++) {
        int rl = ty + 16 * jm;
        float si = g_DV2[i0 + rl] * W0;
        #pragma unroll
        for (int jn = 0; jn < 4; jn++) {
            int cl = lane + 32 * jn;
            float v = (float)acc[jm][jn] * si * g_DV2[j0 + cl];
            G[(size_t)(i0 + rl) * N_NODES + j0 + cl] = v;
            if (offd) sT[cl * TSTR + rl] = v;
        }
    }
    if (offd) {
        __syncthreads();
        #pragma unroll
        for (int t2 = tid; t2 < 4096; t2 += 512) {
            int jr = t2 >> 5, ic = (t2 & 31) << 2;
            float4 v = *(const float4*)&sT[jr * TSTR + ic];
            *(float4*)&G[(size_t)(j0 + jr) * N_NODES + i0 + ic] = v;
        }
    }
}

// =====================================================================
// Kernel 5: exact correction for deviant edges (de != 818); usually no-op
// =====================================================================
__global__ __launch_bounds__(256) void k_fix(float* __restrict__ G)
{
    const int d = blockIdx.x;
    if (d >= g_nDev) return;
    const int e = g_devE[d];
    const int de = g_devDE[d];
    const float delta = 1.0f / (float)de - W0;

    __shared__ int mem[2048];
    __shared__ int cnt;
    if (threadIdx.x == 0) cnt = 0;
    __syncthreads();
    for (int n = threadIdx.x; n < N_NODES; n += 256)
        if ((g_Hn[(size_t)n * 32 + (e >> 5)] >> (e & 31)) & 1u) {
            int p = atomicAdd(&cnt, 1); mem[p] = n;
        }
    __syncthreads();
    const int m = cnt;
    for (int idx = threadIdx.x; idx < m * m; idx += 256) {
        int i = mem[idx / m], j = mem[idx % m];
        atomicAdd(&G[(size_t)i * N_NODES + j], delta * g_DV2[i] * g_DV2[j]);
    }
}

// =====================================================================
extern "C" void kernel_launch(void* const* d_in, const int* in_sizes, int n_in,
                              void* d_out, int out_size)
{
    const float* x  = (const float*)d_in[0];
    const int*   y  = (const int*)d_in[1];
    const float* hp = (const float*)d_in[2];
    float* out = (float*)d_out;

    const int smemBytes = 128 * TSTR * (int)sizeof(float);  // 67584 >= 33024 stage
    cudaFuncSetAttribute(k_gemm, cudaFuncAttributeMaxDynamicSharedMemorySize, smemBytes);

    k_simi<<<dim3(N_NODES / 128, E_EDGES / 64), 256>>>(x, y, hp);
    k_select<<<E_EDGES, 256>>>();
    k_pack_dv<<<256, 256>>>();
    k_gemm<<<2080, 512, smemBytes>>>(out);
    k_fix<<<128, 256>>>(out);

    size_t gElems = (size_t)N_NODES * N_NODES;
    if ((size_t)out_size >= gElems + (size_t)N_NODES * ZD) {
        cudaMemcpyAsync(out + gElems, x, (size_t)N_NODES * ZD * sizeof(float),
                        cudaMemcpyDeviceToDevice);
    }
}

// round 14
// speedup vs baseline: 1.0247x; 1.0247x over previous
#include <cuda_runtime.h>
#include <cuda_bf16.h>
#include <cstdint>

#define E_EDGES 1024
#define N_NODES 8192
#define ZD      256
#define KK_RANK 819
#define DE_NOM  818
#define W0      (1.0f/818.0f)

// ---- scratch ----
__device__ float    g_simi[(size_t)E_EDGES * N_NODES];  // 32 MB [e][n]
__device__ unsigned g_Hbt[256 * E_EDGES];                // bitmask [n/32][e]
__device__ unsigned g_Hn[(size_t)N_NODES * 32];          // node-major edge bits [n][32]
__device__ float    g_DV2[N_NODES];
__device__ int      g_nDev;
__device__ int      g_devE[E_EDGES];
__device__ int      g_devDE[E_EDGES];

// packed fp32x2 FMA (Blackwell)
__device__ __forceinline__ void ffma2(unsigned long long &d,
                                      unsigned long long a, unsigned long long b)
{
    asm volatile("fma.rn.f32x2 %0, %1, %2, %0;" : "+l"(d) : "l"(a), "l"(b));
}
__device__ __forceinline__ unsigned long long pack2(float v)
{
    unsigned long long r;
    asm("mov.b64 %0, {%1, %1};" : "=l"(r) : "f"(v));
    return r;
}
__device__ __forceinline__ unsigned lop3_xor3(unsigned a, unsigned b, unsigned c)
{
    unsigned d;
    asm("lop3.b32 %0, %1, %2, %3, 0x96;" : "=r"(d) : "r"(a), "r"(b), "r"(c));
    return d;
}
__device__ __forceinline__ unsigned lop3_maj(unsigned a, unsigned b, unsigned c)
{
    unsigned d;
    asm("lop3.b32 %0, %1, %2, %3, 0xE8;" : "=r"(d) : "r"(a), "r"(b), "r"(c));
    return d;
}

// =====================================================================
// Kernel 1: simi = hyper_clss @ x^T  (fp32, f32x2-packed FMA)
// =====================================================================
__global__ __launch_bounds__(256) void k_simi(
    const float* __restrict__ x, const int* __restrict__ y,
    const float* __restrict__ hp)
{
    if (blockIdx.x == 0 && blockIdx.y == 0 && threadIdx.x == 0) g_nDev = 0;

    __shared__ float As[32][65];
    __shared__ float Bs[32][130];
    const int be = blockIdx.y * 64, bn = blockIdx.x * 128;
    const int tid = threadIdx.x;
    const int ty = tid >> 4, tx = tid & 15;

    unsigned long long acc2[4][4];
    #pragma unroll
    for (int i = 0; i < 4; i++)
        #pragma unroll
        for (int j = 0; j < 4; j++) acc2[i][j] = 0ull;

    for (int k0 = 0; k0 < ZD; k0 += 32) {
        #pragma unroll
        for (int p = 0; p < 2; p++) {
            int idx = tid + p * 256;
            int e = idx >> 3, k4 = (idx & 7) << 2;
            int ge = be + e;
            int row = y[ge >> 4] * 16 + (ge & 15);
            float4 v = *(const float4*)(hp + (size_t)row * ZD + k0 + k4);
            As[k4+0][e] = v.x; As[k4+1][e] = v.y; As[k4+2][e] = v.z; As[k4+3][e] = v.w;
        }
        #pragma unroll
        for (int p = 0; p < 4; p++) {
            int idx = tid + p * 256;
            int n = idx >> 3, k4 = (idx & 7) << 2;
            float4 v = *(const float4*)(x + (size_t)(bn + n) * ZD + k0 + k4);
            Bs[k4+0][n] = v.x; Bs[k4+1][n] = v.y; Bs[k4+2][n] = v.z; Bs[k4+3][n] = v.w;
        }
        __syncthreads();
        #pragma unroll
        for (int k = 0; k < 32; k++) {
            unsigned long long ad[4], bd[4];
            #pragma unroll
            for (int mi = 0; mi < 4; mi++) ad[mi] = pack2(As[k][ty + 16 * mi]);
            #pragma unroll
            for (int nj = 0; nj < 4; nj++)
                bd[nj] = *(const unsigned long long*)&Bs[k][2 * tx + 32 * nj];
            #pragma unroll
            for (int mi = 0; mi < 4; mi++)
                #pragma unroll
                for (int nj = 0; nj < 4; nj++)
                    ffma2(acc2[mi][nj], ad[mi], bd[nj]);
        }
        __syncthreads();
    }
    #pragma unroll
    for (int mi = 0; mi < 4; mi++)
        #pragma unroll
        for (int nj = 0; nj < 4; nj++) {
            unsigned lo = (unsigned)(acc2[mi][nj] & 0xFFFFFFFFull);
            unsigned hi = (unsigned)(acc2[mi][nj] >> 32);
            float2 v = make_float2(__uint_as_float(lo), __uint_as_float(hi));
            *(float2*)&g_simi[(size_t)(be + ty + 16 * mi) * N_NODES + bn + 2 * tx + 32 * nj] = v;
        }
}

// =====================================================================
// Kernel 2: exact radix select; warp-0 suffix scan (2 barriers/level);
// race-free winner update (snapshot -> barrier -> unique write)
// =====================================================================
__global__ __launch_bounds__(256) void k_select()
{
    __shared__ unsigned su[N_NODES];
    __shared__ unsigned hist[256];
    __shared__ unsigned sfx[256];
    __shared__ unsigned s_bin, s_r, s_above;

    const int e = blockIdx.x;
    const int t = threadIdx.x;
    const int lane = t & 31;
    const float* row = g_simi + (size_t)e * N_NODES;

    #pragma unroll 4
    for (int i = 0; i < 32; i++) {
        unsigned b = __float_as_uint(row[i * 256 + t]);
        su[i * 256 + t] = (b & 0x80000000u) ? ~b : (b | 0x80000000u);
    }
    if (t == 0) { s_r = KK_RANK; s_above = 0; }
    __syncthreads();

    unsigned prefix = 0, pmask = 0;
    for (int level = 0; level < 4; level++) {
        int shift = 24 - 8 * level;
        hist[t] = 0;
        __syncthreads();
        #pragma unroll 4
        for (int i = 0; i < 32; i++) {
            unsigned u = su[i * 256 + t];
            if ((u & pmask) == prefix) atomicAdd(&hist[(u >> shift) & 0xFFu], 1u);
        }
        __syncthreads();

        // warp 0: inclusive suffix-sum of hist -> sfx (8 bins per lane)
        if (t < 32) {
            unsigned h[8], loc[8];
            #pragma unroll
            for (int j = 0; j < 8; j++) h[j] = hist[8 * lane + j];
            unsigned run = 0;
            #pragma unroll
            for (int j = 7; j >= 0; j--) { run += h[j]; loc[j] = run; }
            // inclusive suffix scan of per-lane totals across the warp
            unsigned suf = run;
            #pragma unroll
            for (int off = 1; off < 32; off <<= 1) {
                unsigned v = __shfl_down_sync(0xFFFFFFFFu, suf, off);
                if (lane + off < 32) suf += v;
            }
            unsigned beyond = suf - run;   // sum over groups with index > lane
            #pragma unroll
            for (int j = 0; j < 8; j++) sfx[8 * lane + j] = loc[j] + beyond;
        }
        __syncthreads();

        const unsigned r_cur = s_r;
        const unsigned nxt   = (t < 255) ? sfx[t + 1] : 0u;
        const bool winner    = (sfx[t] >= r_cur) && (nxt < r_cur);
        __syncthreads();
        if (winner) {
            s_bin = (unsigned)t;
            s_r = r_cur - nxt;
            s_above += nxt;
        }
        __syncthreads();
        prefix |= (s_bin << shift);
        pmask  |= (0xFFu << shift);
        __syncthreads();
    }

    const unsigned thr = prefix;
    const unsigned de  = s_above;

    unsigned v = 0;
    #pragma unroll
    for (int b = 0; b < 32; b++)
        v |= (su[32 * t + b] > thr) ? (1u << b) : 0u;
    g_Hbt[t * E_EDGES + e] = v;

    if (t == 0 && de != DE_NOM) {
        int idx = atomicAdd(&g_nDev, 1);
        g_devE[idx] = e; g_devDE[idx] = (int)de;
    }
}

// =====================================================================
// Kernel 3: bit transpose -> node-major edge masks g_Hn[n][32] + DV2.
// =====================================================================
__global__ __launch_bounds__(256) void k_pack_dv()
{
    const int w = blockIdx.x;
    const int t = threadIdx.x;
    const int warp = t >> 5, lane = t & 31;
    __shared__ int s_cnt[32];
    if (t < 32) s_cnt[t] = 0;
    __syncthreads();

    int myCnt = 0;
    #pragma unroll
    for (int i = 0; i < 4; i++) {
        int ew = warp + 8 * i;
        unsigned v = g_Hbt[w * E_EDGES + ew * 32 + lane];
        #pragma unroll
        for (int b = 0; b < 32; b++) {
            unsigned word = __ballot_sync(0xFFFFFFFFu, (v >> b) & 1u);
            if (lane == b) {
                g_Hn[(size_t)(w * 32 + b) * 32 + ew] = word;
                myCnt += __popc(word);
            }
        }
    }
    atomicAdd(&s_cnt[lane], myCnt);
    __syncthreads();
    if (t < 32) g_DV2[w * 32 + t] = rsqrtf((float)s_cnt[t]);
}

// =====================================================================
// Kernel 4: O = H^T H via Harley-Seal CSA popcount (exact)
// 128x128 tiles; 512 threads; 8x4 accs/thread; HS-2 over word pairs.
// (R12 version — best measured: 213.7 us)
// =====================================================================
#define TSTR 132

__global__ __launch_bounds__(512, 1) void k_gemm(float* __restrict__ G)
{
    int b = blockIdx.x;
    int bi = (int)(64.5f - sqrtf(64.5f * 64.5f - 2.0f * (float)b));
    while (64 * bi - bi * (bi - 1) / 2 > b) bi--;
    while (64 * (bi + 1) - (bi + 1) * bi / 2 <= b) bi++;
    const int bj = bi + (b - (64 * bi - bi * (bi - 1) / 2));

    extern __shared__ char dynsm[];
    unsigned* sA = (unsigned*)dynsm;            // [32 ew][128 row]
    unsigned* sB = sA + 32 * 128;
    float*    sT = (float*)dynsm;               // [128][TSTR] floats (reuse)

    const int i0 = bi * 128, j0 = bj * 128;
    const int tid = threadIdx.x;
    const int lane = tid & 31;                  // col base
    const int ty = tid >> 5;                    // row base 0..15

    #pragma unroll
    for (int u = 0; u < 2; u++) {
        int idx = tid * 2 + u;                  // 0..1023
        int r = idx >> 3, q = (idx & 7) << 2;
        uint4 va = *(const uint4*)(g_Hn + (size_t)(i0 + r) * 32 + q);
        uint4 vb = *(const uint4*)(g_Hn + (size_t)(j0 + r) * 32 + q);
        sA[(q+0)*128 + r] = va.x; sA[(q+1)*128 + r] = va.y;
        sA[(q+2)*128 + r] = va.z; sA[(q+3)*128 + r] = va.w;
        sB[(q+0)*128 + r] = vb.x; sB[(q+1)*128 + r] = vb.y;
        sB[(q+2)*128 + r] = vb.z; sB[(q+3)*128 + r] = vb.w;
    }
    __syncthreads();

    int acc[8][4];
    unsigned ones[8][4];
    #pragma unroll
    for (int jm = 0; jm < 8; jm++)
        #pragma unroll
        for (int jn = 0; jn < 4; jn++) { acc[jm][jn] = 0; ones[jm][jn] = 0u; }

    #pragma unroll
    for (int ew = 0; ew < 32; ew += 2) {
        unsigned a0[8], a1[8], b0[4], b1[4];
        #pragma unroll
        for (int jm = 0; jm < 8; jm++) {
            a0[jm] = sA[ ew      * 128 + ty + 16 * jm];
            a1[jm] = sA[(ew + 1) * 128 + ty + 16 * jm];
        }
        #pragma unroll
        for (int jn = 0; jn < 4; jn++) {
            b0[jn] = sB[ ew      * 128 + lane + 32 * jn];
            b1[jn] = sB[(ew + 1) * 128 + lane + 32 * jn];
        }
        #pragma unroll
        for (int jm = 0; jm < 8; jm++)
            #pragma unroll
            for (int jn = 0; jn < 4; jn++) {
                unsigned t0 = a0[jm] & b0[jn];
                unsigned t1 = a1[jm] & b1[jn];
                unsigned o  = ones[jm][jn];
                ones[jm][jn] = lop3_xor3(o, t0, t1);
                acc[jm][jn] += __popc(lop3_maj(o, t0, t1));
            }
    }
    #pragma unroll
    for (int jm = 0; jm < 8; jm++)
        #pragma unroll
        for (int jn = 0; jn < 4; jn++)
            acc[jm][jn] = 2 * acc[jm][jn] + __popc(ones[jm][jn]);

    __syncthreads();   // done reading sA/sB before sT reuse

    const bool offd = (bi != bj);
    #pragma unroll
    for (int jm = 0; jm < 8; jm++) {
        int rl = ty + 16 * jm;
        float si = g_DV2[i0 + rl] * W0;
        #pragma unroll
        for (int jn = 0; jn < 4; jn++) {
            int cl = lane + 32 * jn;
            float v = (float)acc[jm][jn] * si * g_DV2[j0 + cl];
            G[(size_t)(i0 + rl) * N_NODES + j0 + cl] = v;
            if (offd) sT[cl * TSTR + rl] = v;
        }
    }
    if (offd) {
        __syncthreads();
        #pragma unroll
        for (int t2 = tid; t2 < 4096; t2 += 512) {
            int jr = t2 >> 5, ic = (t2 & 31) << 2;
            float4 v = *(const float4*)&sT[jr * TSTR + ic];
            *(float4*)&G[(size_t)(j0 + jr) * N_NODES + i0 + ic] = v;
        }
    }
}

// =====================================================================
// Kernel 5: exact correction for deviant edges (de != 818); usually no-op
// =====================================================================
__global__ __launch_bounds__(256) void k_fix(float* __restrict__ G)
{
    const int d = blockIdx.x;
    if (d >= g_nDev) return;
    const int e = g_devE[d];
    const int de = g_devDE[d];
    const float delta = 1.0f / (float)de - W0;

    __shared__ int mem[2048];
    __shared__ int cnt;
    if (threadIdx.x == 0) cnt = 0;
    __syncthreads();
    for (int n = threadIdx.x; n < N_NODES; n += 256)
        if ((g_Hn[(size_t)n * 32 + (e >> 5)] >> (e & 31)) & 1u) {
            int p = atomicAdd(&cnt, 1); mem[p] = n;
        }
    __syncthreads();
    const int m = cnt;
    for (int idx = threadIdx.x; idx < m * m; idx += 256) {
        int i = mem[idx / m], j = mem[idx % m];
        atomicAdd(&G[(size_t)i * N_NODES + j], delta * g_DV2[i] * g_DV2[j]);
    }
}

// =====================================================================
extern "C" void kernel_launch(void* const* d_in, const int* in_sizes, int n_in,
                              void* d_out, int out_size)
{
    const float* x  = (const float*)d_in[0];
    const int*   y  = (const int*)d_in[1];
    const float* hp = (const float*)d_in[2];
    float* out = (float*)d_out;

    const int smemBytes = 128 * TSTR * (int)sizeof(float);
    cudaFuncSetAttribute(k_gemm, cudaFuncAttributeMaxDynamicSharedMemorySize, smemBytes);

    k_simi<<<dim3(N_NODES / 128, E_EDGES / 64), 256>>>(x, y, hp);
    k_select<<<E_EDGES, 256>>>();
    k_pack_dv<<<256, 256>>>();
    k_gemm<<<2080, 512, smemBytes>>>(out);
    k_fix<<<128, 256>>>(out);

    size_t gElems = (size_t)N_NODES * N_NODES;
    if ((size_t)out_size >= gElems + (size_t)N_NODES * ZD) {
        cudaMemcpyAsync(out + gElems, x, (size_t)N_NODES * ZD * sizeof(float),
                        cudaMemcpyDeviceToDevice);
    }
}